// round 6
// baseline (speedup 1.0000x reference)
#include <cuda_runtime.h>
#include <cuda_bf16.h>
#include <math.h>
#include <stdint.h>

// ---------------------------------------------------------------------------
// Swin3D ViT block. bf16 mma.sync GEMMs, 256x128 block / 64x64 warp tiles
// (smem-traffic-optimal for mma.sync), ldmatrix.x4, double-buffered cp.async.
// ---------------------------------------------------------------------------

#define TOK      32768
#define C_       384
#define SIXC     2304
#define NOISE_   256
#define HEADS_   12
#define NWIN     512
#define EPS_     1e-5f

// scratch
__device__ float g_params[2 * SIXC];
__device__ float g_x1[TOK * C_];
__device__ __nv_bfloat16 g_xmod[TOK * C_];
__device__ __nv_bfloat16 g_qkv[TOK * 3 * C_];
__device__ __nv_bfloat16 g_attn[TOK * C_];
__device__ __nv_bfloat16 g_h[TOK * 4 * C_];
__device__ __nv_bfloat16 g_wq[3 * C_ * C_];
__device__ __nv_bfloat16 g_wo[C_ * C_];
__device__ __nv_bfloat16 g_w1[4 * C_ * C_];
__device__ __nv_bfloat16 g_w2[4 * C_ * C_];

// ---------------------------------------------------------------------------
__device__ __forceinline__ uint32_t packbf(float lo, float hi) {
    __nv_bfloat162 t = __floats2bfloat162_rn(lo, hi);
    return *(uint32_t*)&t;
}

__device__ __forceinline__ void mmabf(float* d, const uint32_t* a, const uint32_t* b) {
    asm volatile(
        "mma.sync.aligned.m16n8k16.row.col.f32.bf16.bf16.f32 "
        "{%0,%1,%2,%3}, {%4,%5,%6,%7}, {%8,%9}, {%0,%1,%2,%3};"
        : "+f"(d[0]), "+f"(d[1]), "+f"(d[2]), "+f"(d[3])
        : "r"(a[0]), "r"(a[1]), "r"(a[2]), "r"(a[3]), "r"(b[0]), "r"(b[1]));
}

__device__ __forceinline__ void ldsm4(uint32_t* r, const uint32_t* sptr) {
    uint32_t a = (uint32_t)__cvta_generic_to_shared(sptr);
    asm volatile("ldmatrix.sync.aligned.m8n8.x4.shared.b16 {%0,%1,%2,%3}, [%4];"
                 : "=r"(r[0]), "=r"(r[1]), "=r"(r[2]), "=r"(r[3]) : "r"(a));
}

__device__ __forceinline__ void cp16(void* sptr, const void* gptr) {
    unsigned sa = (unsigned)__cvta_generic_to_shared(sptr);
    asm volatile("cp.async.ca.shared.global [%0], [%1], 16;" :: "r"(sa), "l"(gptr));
}

// ---------------------------------------------------------------------------
// weight conversion
// ---------------------------------------------------------------------------
#define NWQ (3 * C_ * C_)
#define NWO (C_ * C_)
#define NW1 (4 * C_ * C_)
#define NW2 (4 * C_ * C_)
__global__ __launch_bounds__(256) void cvt_kernel(
    const float* __restrict__ wq, const float* __restrict__ wo,
    const float* __restrict__ w1, const float* __restrict__ w2)
{
    int i = blockIdx.x * 256 + threadIdx.x;
    if (i < NWQ) { g_wq[i] = __float2bfloat16(wq[i]); return; }
    i -= NWQ;
    if (i < NWO) { g_wo[i] = __float2bfloat16(wo[i]); return; }
    i -= NWO;
    if (i < NW1) { g_w1[i] = __float2bfloat16(w1[i]); return; }
    i -= NW1;
    if (i < NW2) { g_w2[i] = __float2bfloat16(w2[i]); }
}

// ---------------------------------------------------------------------------
// AdaLN params
// ---------------------------------------------------------------------------
__global__ __launch_bounds__(256) void ada_kernel(
    const float* __restrict__ xn, const float* __restrict__ aw,
    const float* __restrict__ ab)
{
    __shared__ float s[NOISE_];
    int b  = blockIdx.x / 9;
    int jb = blockIdx.x % 9;
    float v = xn[b * NOISE_ + threadIdx.x];
    s[threadIdx.x] = v / (1.f + expf(-v));
    __syncthreads();
    int j = jb * 256 + threadIdx.x;
    const float* w = aw + (size_t)j * NOISE_;
    float acc = ab[j];
#pragma unroll 8
    for (int i = 0; i < NOISE_; i++) acc += w[i] * s[i];
    g_params[b * SIXC + j] = acc;
}

// ---------------------------------------------------------------------------
// LN + modulate -> bf16
// ---------------------------------------------------------------------------
__global__ __launch_bounds__(256) void ln_mod_kernel(
    const float* __restrict__ x, int shiftOff, int scaleOff,
    uint32_t* __restrict__ out)
{
    int warp = threadIdx.x >> 5, lane = threadIdx.x & 31;
    int tok = blockIdx.x * 8 + warp;
    int b = tok >> 14;
    const float4* xr = (const float4*)(x + (size_t)tok * C_);
    float4 v[3];
    float s = 0.f;
#pragma unroll
    for (int i = 0; i < 3; i++) {
        v[i] = xr[lane + 32 * i];
        s += v[i].x + v[i].y + v[i].z + v[i].w;
    }
#pragma unroll
    for (int o = 16; o; o >>= 1) s += __shfl_xor_sync(0xffffffffu, s, o);
    float mean = s * (1.f / 384.f);
    float sq = 0.f;
#pragma unroll
    for (int i = 0; i < 3; i++) {
        float dx = v[i].x - mean, dy = v[i].y - mean;
        float dz = v[i].z - mean, dw = v[i].w - mean;
        sq += dx * dx + dy * dy + dz * dz + dw * dw;
    }
#pragma unroll
    for (int o = 16; o; o >>= 1) sq += __shfl_xor_sync(0xffffffffu, sq, o);
    float rstd = rsqrtf(sq * (1.f / 384.f) + EPS_);
    const float4* sh4 = (const float4*)(g_params + b * SIXC + shiftOff);
    const float4* sc4 = (const float4*)(g_params + b * SIXC + scaleOff);
    uint32_t* orow = out + (size_t)tok * (C_ / 2);
#pragma unroll
    for (int i = 0; i < 3; i++) {
        int idx = lane + 32 * i;
        float4 s4 = sh4[idx], m4 = sc4[idx];
        float y0 = (v[i].x - mean) * rstd * (1.f + m4.x) + s4.x;
        float y1 = (v[i].y - mean) * rstd * (1.f + m4.y) + s4.y;
        float y2 = (v[i].z - mean) * rstd * (1.f + m4.z) + s4.z;
        float y3 = (v[i].w - mean) * rstd * (1.f + m4.w) + s4.w;
        orow[idx * 2]     = packbf(y0, y1);
        orow[idx * 2 + 1] = packbf(y2, y3);
    }
}

// ---------------------------------------------------------------------------
// bf16 GEMM: C[M,N] = A[M,K] @ W[N,K]^T (+bias) + epilogue.
// Block 256x128, 256 threads = 8 warps (4 M x 2 N), warp tile 64x64.
// BK=32 elems (16 u32). ldmatrix.x4 fragments, double-buffered cp.async.
// MODE 0: bias -> bf16   MODE 1: gelu -> bf16   MODE 2: res+gate -> fp32
// ---------------------------------------------------------------------------
#define AOFF(buf, r, k) ((buf) * (256 * 20) + (r) * 20 + (k))
#define BOFF(buf, r, k) ((buf) * (128 * 20) + (r) * 20 + (k))
#define GEMM_SMEM (2 * (256 + 128) * 20 * 4)   // 61440 bytes

template <int MODE>
__global__ __launch_bounds__(256, 1) void gemm_bf(
    const uint32_t* __restrict__ A, const uint32_t* __restrict__ Bw,
    const float* __restrict__ bias, void* __restrict__ Cout,
    int M, int N, int K2,
    const float* __restrict__ res, int gateOff)
{
    extern __shared__ uint32_t sm[];
    uint32_t* As = sm;                 // [2][256][20]
    uint32_t* Bs = sm + 2 * 256 * 20;  // [2][128][20]

    int tid  = threadIdx.x;
    int warp = tid >> 5, lane = tid & 31;
    int g = lane >> 2, c = lane & 3;
    int wm = (warp & 3) * 64;        // 4 warps over M
    int wn = (warp >> 2) * 64;       // 2 warps over N
    int bm = blockIdx.y * 256;
    int bn = blockIdx.x * 128;

    int a_row = (lane & 15);
    int a_ko  = (lane >> 4) * 4;
    int b_row = (lane & 7) + ((lane >> 4) & 1) * 8;
    int b_ko  = ((lane >> 3) & 1) * 4;

    float acc[4][8][4];
#pragma unroll
    for (int i = 0; i < 4; i++)
#pragma unroll
        for (int j = 0; j < 8; j++)
#pragma unroll
            for (int t = 0; t < 4; t++) acc[i][j][t] = 0.f;

    int nk = K2 >> 4;   // BK = 16 u32 = 32 bf16

    // stage tile 0: A 1024 cp16 (4/thread), B 512 cp16 (2/thread)
#pragma unroll
    for (int i = 0; i < 4; i++) {
        int idx = tid + 256 * i;
        int row = idx >> 2, c4 = (idx & 3) << 2;
        cp16(&As[AOFF(0, row, c4)], A + (size_t)(bm + row) * K2 + c4);
    }
#pragma unroll
    for (int i = 0; i < 2; i++) {
        int idx = tid + 256 * i;
        int row = idx >> 2, c4 = (idx & 3) << 2;
        cp16(&Bs[BOFF(0, row, c4)], Bw + (size_t)(bn + row) * K2 + c4);
    }
    asm volatile("cp.async.commit_group;");

    for (int kt = 0; kt < nk; kt++) {
        int buf = kt & 1;
        if (kt + 1 < nk) {
            int k0 = (kt + 1) << 4;
#pragma unroll
            for (int i = 0; i < 4; i++) {
                int idx = tid + 256 * i;
                int row = idx >> 2, c4 = (idx & 3) << 2;
                cp16(&As[AOFF(buf ^ 1, row, c4)], A + (size_t)(bm + row) * K2 + k0 + c4);
            }
#pragma unroll
            for (int i = 0; i < 2; i++) {
                int idx = tid + 256 * i;
                int row = idx >> 2, c4 = (idx & 3) << 2;
                cp16(&Bs[BOFF(buf ^ 1, row, c4)], Bw + (size_t)(bn + row) * K2 + k0 + c4);
            }
            asm volatile("cp.async.commit_group;");
            asm volatile("cp.async.wait_group 1;");
        } else {
            asm volatile("cp.async.wait_group 0;");
        }
        __syncthreads();

#pragma unroll
        for (int ks = 0; ks < 2; ks++) {
            int kb = ks << 3;
            uint32_t af[4][4];
#pragma unroll
            for (int mt = 0; mt < 4; mt++)
                ldsm4(af[mt], &As[AOFF(buf, wm + mt * 16 + a_row, kb + a_ko)]);
            uint32_t bfr[4][4];
#pragma unroll
            for (int p = 0; p < 4; p++)
                ldsm4(bfr[p], &Bs[BOFF(buf, wn + p * 16 + b_row, kb + b_ko)]);
#pragma unroll
            for (int mt = 0; mt < 4; mt++)
#pragma unroll
                for (int nt = 0; nt < 8; nt++)
                    mmabf(acc[mt][nt], af[mt], &bfr[nt >> 1][(nt & 1) * 2]);
        }
        __syncthreads();
    }

    // epilogue
#pragma unroll
    for (int mt = 0; mt < 4; mt++) {
        int r0 = bm + wm + mt * 16 + g;
#pragma unroll
        for (int nt = 0; nt < 8; nt++) {
            int col = bn + wn + nt * 8 + (c << 1);
            float b0 = bias[col], b1 = bias[col + 1];
#pragma unroll
            for (int half = 0; half < 2; half++) {
                int row = r0 + half * 8;
                float v0 = acc[mt][nt][half * 2 + 0] + b0;
                float v1 = acc[mt][nt][half * 2 + 1] + b1;
                if (MODE == 1) {
                    v0 = 0.5f * v0 * (1.f + erff(v0 * 0.7071067811865476f));
                    v1 = 0.5f * v1 * (1.f + erff(v1 * 0.7071067811865476f));
                }
                if (MODE == 2) {
                    int bb = row >> 14;
                    float g0 = g_params[bb * SIXC + gateOff + col];
                    float g1 = g_params[bb * SIXC + gateOff + col + 1];
                    const float2 rr = *(const float2*)(res + (size_t)row * N + col);
                    *(float2*)((float*)Cout + (size_t)row * N + col) =
                        make_float2(rr.x + g0 * v0, rr.y + g1 * v1);
                } else {
                    ((uint32_t*)Cout)[(size_t)row * (N >> 1) + (col >> 1)] = packbf(v0, v1);
                }
            }
        }
    }
}

// ---------------------------------------------------------------------------
// Windowed attention, bf16 mma.sync. Block = (window, head), 128 threads.
// ---------------------------------------------------------------------------
__global__ __launch_bounds__(128) void attn_kernel(
    const uint32_t* __restrict__ qkv, uint32_t* __restrict__ attn_out)
{
    __shared__ uint32_t Qs[64 * 20];
    __shared__ uint32_t Ks[64 * 20];
    __shared__ __nv_bfloat16 Vt[32 * 72];

    int tid = threadIdx.x;
    int warp = tid >> 5, lane = tid & 31;
    int g = lane >> 2, c = lane & 3;
    int win  = blockIdx.x / HEADS_;
    int head = blockIdx.x % HEADS_;

    int b = win >> 8, rem = win & 255;
    int hb = rem >> 5, rem2 = rem & 31, wb = rem2 >> 2, db = rem2 & 3;
    int base = b * 16384 + hb * 4 * 512 + wb * 4 * 16 + db * 4;

    for (int idx = tid; idx < 1024; idx += 128) {
        int r = idx >> 4, cc = idx & 15;
        int tok = base + (r >> 4) * 512 + ((r >> 2) & 3) * 16 + (r & 3);
        const uint32_t* p = qkv + (size_t)tok * 576 + head * 16 + cc;
        Qs[r * 20 + cc] = p[0];
        Ks[r * 20 + cc] = p[192];
    }
    const __nv_bfloat16* qkvh = (const __nv_bfloat16*)qkv;
    for (int idx = tid; idx < 2048; idx += 128) {
        int r = idx >> 5, hd = idx & 31;
        int tok = base + (r >> 4) * 512 + ((r >> 2) & 3) * 16 + (r & 3);
        Vt[hd * 72 + r] = qkvh[(size_t)tok * 1152 + 768 + head * 32 + hd];
    }
    __syncthreads();

    float sacc[8][4];
#pragma unroll
    for (int i = 0; i < 8; i++)
#pragma unroll
        for (int t = 0; t < 4; t++) sacc[i][t] = 0.f;

    int r0 = warp * 16;
#pragma unroll
    for (int ks = 0; ks < 2; ks++) {
        int kb = ks << 3;
        uint32_t af[4];
        af[0] = Qs[(r0 + g) * 20 + kb + c];
        af[1] = Qs[(r0 + g + 8) * 20 + kb + c];
        af[2] = Qs[(r0 + g) * 20 + kb + c + 4];
        af[3] = Qs[(r0 + g + 8) * 20 + kb + c + 4];
#pragma unroll
        for (int nt = 0; nt < 8; nt++) {
            uint32_t bfr[2];
            bfr[0] = Ks[(nt * 8 + g) * 20 + kb + c];
            bfr[1] = Ks[(nt * 8 + g) * 20 + kb + c + 4];
            mmabf(sacc[nt], af, bfr);
        }
    }

    const float SC = 0.17677669529663687f;
    float slo = 0.f, shi = 0.f;
#pragma unroll
    for (int nt = 0; nt < 8; nt++) {
        sacc[nt][0] = __expf(sacc[nt][0] * SC);
        sacc[nt][1] = __expf(sacc[nt][1] * SC);
        sacc[nt][2] = __expf(sacc[nt][2] * SC);
        sacc[nt][3] = __expf(sacc[nt][3] * SC);
        slo += sacc[nt][0] + sacc[nt][1];
        shi += sacc[nt][2] + sacc[nt][3];
    }
    slo += __shfl_xor_sync(0xffffffffu, slo, 1);
    slo += __shfl_xor_sync(0xffffffffu, slo, 2);
    shi += __shfl_xor_sync(0xffffffffu, shi, 1);
    shi += __shfl_xor_sync(0xffffffffu, shi, 2);

    float o[4][4];
#pragma unroll
    for (int i = 0; i < 4; i++)
#pragma unroll
        for (int t = 0; t < 4; t++) o[i][t] = 0.f;

    const uint32_t* Vt32 = (const uint32_t*)Vt;
#pragma unroll
    for (int kt = 0; kt < 4; kt++) {
        uint32_t pa[4];
        pa[0] = packbf(sacc[2 * kt][0],     sacc[2 * kt][1]);
        pa[1] = packbf(sacc[2 * kt][2],     sacc[2 * kt][3]);
        pa[2] = packbf(sacc[2 * kt + 1][0], sacc[2 * kt + 1][1]);
        pa[3] = packbf(sacc[2 * kt + 1][2], sacc[2 * kt + 1][3]);
#pragma unroll
        for (int nt = 0; nt < 4; nt++) {
            uint32_t bfr[2];
            const uint32_t* vrow = Vt32 + (nt * 8 + g) * 36;
            bfr[0] = vrow[kt * 8 + c];
            bfr[1] = vrow[kt * 8 + c + 4];
            mmabf(o[nt], pa, bfr);
        }
    }

    float inv_lo = 1.f / slo, inv_hi = 1.f / shi;
#pragma unroll
    for (int half = 0; half < 2; half++) {
        int r = r0 + g + half * 8;
        int tok = base + (r >> 4) * 512 + ((r >> 2) & 3) * 16 + (r & 3);
        uint32_t* op = attn_out + (size_t)tok * 192 + head * 16;
        float inv = half ? inv_hi : inv_lo;
#pragma unroll
        for (int nt = 0; nt < 4; nt++)
            op[nt * 4 + c] = packbf(o[nt][half * 2] * inv, o[nt][half * 2 + 1] * inv);
    }
}

// ---------------------------------------------------------------------------
// launch
// ---------------------------------------------------------------------------
extern "C" void kernel_launch(void* const* d_in, const int* in_sizes, int n_in,
                              void* d_out, int out_size)
{
    const float* x      = (const float*)d_in[0];
    const float* xn     = (const float*)d_in[1];
    const float* ada_w  = (const float*)d_in[2];
    const float* ada_b  = (const float*)d_in[3];
    const float* qkv_w  = (const float*)d_in[4];
    const float* qkv_b  = (const float*)d_in[5];
    const float* out_w  = (const float*)d_in[6];
    const float* out_b  = (const float*)d_in[7];
    const float* mlp_w1 = (const float*)d_in[8];
    const float* mlp_b1 = (const float*)d_in[9];
    const float* mlp_w2 = (const float*)d_in[10];
    const float* mlp_b2 = (const float*)d_in[11];
    float* out = (float*)d_out;

    void *p_xmod, *p_qkv, *p_attn, *p_x1, *p_h, *p_wq, *p_wo, *p_w1, *p_w2;
    cudaGetSymbolAddress(&p_xmod, g_xmod);
    cudaGetSymbolAddress(&p_qkv,  g_qkv);
    cudaGetSymbolAddress(&p_attn, g_attn);
    cudaGetSymbolAddress(&p_x1,   g_x1);
    cudaGetSymbolAddress(&p_h,    g_h);
    cudaGetSymbolAddress(&p_wq,   g_wq);
    cudaGetSymbolAddress(&p_wo,   g_wo);
    cudaGetSymbolAddress(&p_w1,   g_w1);
    cudaGetSymbolAddress(&p_w2,   g_w2);

    cudaFuncSetAttribute(gemm_bf<0>, cudaFuncAttributeMaxDynamicSharedMemorySize, GEMM_SMEM);
    cudaFuncSetAttribute(gemm_bf<1>, cudaFuncAttributeMaxDynamicSharedMemorySize, GEMM_SMEM);
    cudaFuncSetAttribute(gemm_bf<2>, cudaFuncAttributeMaxDynamicSharedMemorySize, GEMM_SMEM);

    cvt_kernel<<<(NWQ + NWO + NW1 + NW2) / 256, 256>>>(qkv_w, out_w, mlp_w1, mlp_w2);
    ada_kernel<<<18, 256>>>(xn, ada_w, ada_b);
    ln_mod_kernel<<<TOK / 8, 256>>>(x, 0, C_, (uint32_t*)p_xmod);

    {   // QKV: [32768,384] @ [1152,384]^T -> bf16
        dim3 grid((3 * C_) / 128, TOK / 256);
        gemm_bf<0><<<grid, 256, GEMM_SMEM>>>((const uint32_t*)p_xmod, (const uint32_t*)p_wq,
                                             qkv_b, p_qkv, TOK, 3 * C_, C_ / 2, nullptr, 0);
    }

    attn_kernel<<<NWIN * HEADS_, 128>>>((const uint32_t*)p_qkv, (uint32_t*)p_attn);

    {   // out proj + gate1 + residual -> fp32
        dim3 grid(C_ / 128, TOK / 256);
        gemm_bf<2><<<grid, 256, GEMM_SMEM>>>((const uint32_t*)p_attn, (const uint32_t*)p_wo,
                                             out_b, p_x1, TOK, C_, C_ / 2, x, 2 * C_);
    }

    ln_mod_kernel<<<TOK / 8, 256>>>((const float*)p_x1, 3 * C_, 4 * C_, (uint32_t*)p_xmod);

    {   // MLP1 + GELU -> bf16
        dim3 grid((4 * C_) / 128, TOK / 256);
        gemm_bf<1><<<grid, 256, GEMM_SMEM>>>((const uint32_t*)p_xmod, (const uint32_t*)p_w1,
                                             mlp_b1, p_h, TOK, 4 * C_, C_ / 2, nullptr, 0);
    }

    {   // MLP2 + gate2 + residual -> fp32
        dim3 grid(C_ / 128, TOK / 256);
        gemm_bf<2><<<grid, 256, GEMM_SMEM>>>((const uint32_t*)p_h, (const uint32_t*)p_w2,
                                             mlp_b2, out, TOK, C_, 2 * C_, (const float*)p_x1, 5 * C_);
    }
}